// round 11
// baseline (speedup 1.0000x reference)
#include <cuda_runtime.h>

// ---------------------------------------------------------------------------
// QuantumBranch R10: R8's proven 1-elem/thread LDCU qmain + (1,C,S) basis
// (validated in R9), plus a parallelized setup V-build (gate steps applied
// matrix-wide by 128/64 threads instead of a 16-thread serial chain).
//   z_w - z_0 = v~^T D~_w u~, v~/u~ = (1,C,S) Kronecker pairs (leading 1
//   implicit -> 8-wide rows + const). Constants in __constant__ (uniform
//   datapath). qi = e * rsqrt(e^T M''' e). Warp-local transpose epilogue.
// ---------------------------------------------------------------------------

typedef unsigned long long u64;

__device__    float g_CONST[260];       // [0..243): D~1,D~2,D~3 (81 each); [243..259): M'''
__constant__  float cCONST[260];
__device__    float4 g_epi4[16][6];     // per dim-quad: 8 WA, 8 WB, 4 beta, pad

__device__ __forceinline__ u64 pk2(float a, float b) {
    u64 r; asm("mov.b64 %0,{%1,%2};" : "=l"(r) : "f"(a), "f"(b)); return r;
}
__device__ __forceinline__ u64 f2fma(u64 a, u64 b, u64 c) {
    u64 d; asm("fma.rn.f32x2 %0,%1,%2,%3;" : "=l"(d) : "l"(a), "l"(b), "l"(c)); return d;
}

__device__ __forceinline__ float wsum(float v) {
    #pragma unroll
    for (int o = 16; o; o >>= 1) v += __shfl_xor_sync(0xffffffffu, v, o);
    return v;
}

__global__ void setup_kernel(const float* __restrict__ wts,
                             const float* __restrict__ W,
                             const float* __restrict__ b,
                             const float* __restrict__ gm,
                             const float* __restrict__ bt)
{
    __shared__ float2 sv[16][16];    // [col j][row k] = V[k][j]
    __shared__ float2 sGt[8][3];     // per gate: {sa,ca},{sb,cb},{st,ct}
    __shared__ float  sG[3][256];    // per (i,j) pair: G_w[i][j]
    __shared__ float  sD[243];       // D'_w in monomial basis
    int tid = threadIdx.x;

    // ---- step (a): parallel gate sincos (24 thr) + identity init (all) +
    //      LayerNorm folds (warp 2, tid 64..95) ----
    if (tid < 24) {
        int g = tid / 3, part = tid % 3;
        const float* gp = wts + g * 3;
        float phi = gp[0], th = gp[1], om = gp[2];
        float arg = (part == 0) ? 0.5f * (phi + om)
                  : (part == 1) ? 0.5f * (phi - om)
                                : 0.5f * th;
        float s, c; __sincosf(arg, &s, &c);
        sGt[g][part] = make_float2(s, c);
    }
    {
        int j = tid >> 4, k = tid & 15;
        sv[j][k] = make_float2(j == k ? 1.f : 0.f, 0.f);
    }
    if (tid >= 64 && tid < 96) {
        int lane = tid - 64;
        const float inv64 = 1.f / 64.f;
        float wa[4], wb[4];
        #pragma unroll
        for (int i = 0; i < 4; i++) { wa[i] = W[lane * 4 + i]; wb[i] = W[(lane + 32) * 4 + i]; }
        float ba = b[lane], bbv = b[lane + 32];

        float cm[4];
        #pragma unroll
        for (int i = 0; i < 4; i++) cm[i] = wsum(wa[i] + wb[i]) * inv64;
        float bm = wsum(ba + bbv) * inv64;
        #pragma unroll
        for (int i = 0; i < 4; i++) { wa[i] -= cm[i]; wb[i] -= cm[i]; }
        ba -= bm; bbv -= bm;

        float M[4][4];
        #pragma unroll
        for (int i = 0; i < 4; i++) {
            #pragma unroll
            for (int k = 0; k < 4; k++) {
                if (k >= i) {
                    float v = wsum(wa[i] * wa[k] + wb[i] * wb[k]) * inv64;
                    M[i][k] = v; M[k][i] = v;
                }
            }
        }
        float vv[4];
        #pragma unroll
        for (int i = 0; i < 4; i++) vv[i] = wsum(wa[i] * ba + wb[i] * bbv) * (2.f * inv64);
        float vc = wsum(ba * ba + bbv * bbv) * inv64;

        if (lane == 0) {
            #pragma unroll
            for (int i = 0; i < 4; i++)
                #pragma unroll
                for (int k = 0; k < 4; k++)
                    g_CONST[243 + i * 4 + k] =
                        M[i][k] + 0.5f * (vv[i] + vv[k]) + vc + 1e-5f;
        }

        float ga = gm[lane], gb = gm[lane + 32];
        float bea = bt[lane], beb = bt[lane + 32];
        {
            int d = lane, dqi = d >> 2, r = d & 3;
            float* ep = (float*)&g_epi4[dqi][0];
            int base = (r < 2) ? r : (8 + (r - 2));
            ep[base + 0] = (wa[0] + ba) * ga;
            ep[base + 2] = (wa[1] + ba) * ga;
            ep[base + 4] = (wa[2] + ba) * ga;
            ep[base + 6] = (wa[3] + ba) * ga;
            ep[16 + r]   = bea;
        }
        {
            int d = lane + 32, dqi = d >> 2, r = d & 3;
            float* ep = (float*)&g_epi4[dqi][0];
            int base = (r < 2) ? r : (8 + (r - 2));
            ep[base + 0] = (wb[0] + bbv) * gb;
            ep[base + 2] = (wb[1] + bbv) * gb;
            ep[base + 4] = (wb[2] + bbv) * gb;
            ep[base + 6] = (wb[3] + bbv) * gb;
            ep[16 + r]   = beb;
        }
    }
    __syncthreads();

    // ---- step (b): 8 Rot gates + CNOT rings, applied matrix-wide ----
    #pragma unroll
    for (int l = 0; l < 2; l++) {
        #pragma unroll
        for (int wq = 0; wq < 4; wq++) {
            int g = l * 4 + wq;
            int mask = 8 >> wq;
            if (tid < 128) {
                int p = tid >> 4, j = tid & 15;
                int k = ((p & ~(mask - 1)) << 1) | (p & (mask - 1));
                int k1 = k | mask;
                float sa = sGt[g][0].x, ca = sGt[g][0].y;
                float sb = sGt[g][1].x, cb = sGt[g][1].y;
                float st = sGt[g][2].x, ct = sGt[g][2].y;
                float2 g00 = make_float2( ca * ct, -sa * ct);
                float2 g01 = make_float2(-cb * st, -sb * st);
                float2 g10 = make_float2( cb * st, -sb * st);
                float2 g11 = make_float2( ca * ct,  sa * ct);
                float2 A = sv[j][k], B = sv[j][k1];
                float2 t0, t1;
                t0.x = g00.x * A.x - g00.y * A.y + g01.x * B.x - g01.y * B.y;
                t0.y = g00.x * A.y + g00.y * A.x + g01.x * B.y + g01.y * B.x;
                t1.x = g10.x * A.x - g10.y * A.y + g11.x * B.x - g11.y * B.y;
                t1.y = g10.x * A.y + g10.y * A.x + g11.x * B.y + g11.y * B.x;
                sv[j][k] = t0; sv[j][k1] = t1;
            }
            __syncthreads();
        }
        int r = (l == 0) ? 1 : 2;
        #pragma unroll
        for (int wq = 0; wq < 4; wq++) {
            int mc = 8 >> wq, mt = 8 >> ((wq + r) & 3);
            if (tid < 64) {
                int pid = tid >> 4, j = tid & 15;
                int fm = 15 & ~mc & ~mt;
                int fb0 = fm & (-fm), fb1 = fm ^ fb0;
                int k = mc | ((pid & 1) ? fb0 : 0) | ((pid >> 1) ? fb1 : 0);
                int k1 = k | mt;
                float2 tmp = sv[j][k]; sv[j][k] = sv[j][k1]; sv[j][k1] = tmp;
            }
            __syncthreads();
        }
    }

    // ---- step (c): fold column phase (-i)^popcount(j) ----
    {
        int j = tid >> 4, k = tid & 15;
        int pop = __popc(j) & 3;
        float2 v = sv[j][k], o;
        if      (pop == 0) o = v;
        else if (pop == 1) o = make_float2( v.y, -v.x);
        else if (pop == 2) o = make_float2(-v.x, -v.y);
        else               o = make_float2(-v.y,  v.x);
        sv[j][k] = o;
    }
    __syncthreads();

    // ---- Phase A: per (i,j) pair, G_w[i][j] = sum_k (sigma_w - sigma_0) Re(V*_i V_j)
    {
        int i = tid >> 4, j = tid & 15;
        float g1 = 0.f, g2 = 0.f, g3 = 0.f;
        #pragma unroll
        for (int k = 0; k < 16; k++) {
            float rr = sv[i][k].x * sv[j][k].x + sv[i][k].y * sv[j][k].y;
            float s0 = (k & 8) ? -1.f : 1.f;
            g1 += (((k & 4) ? -1.f : 1.f) - s0) * rr;
            g2 += (((k & 2) ? -1.f : 1.f) - s0) * rr;
            g3 += (((k & 1) ? -1.f : 1.f) - s0) * rr;
        }
        sG[0][tid] = g1; sG[1][tid] = g2; sG[2][tid] = g3;
    }
    __syncthreads();

    // ---- Phase B: D'_w[m9][n9] (monomial basis) ----
    if (tid < 243) {
        int w = tid / 81;
        int mn = tid % 81;
        int m9 = mn / 9, n9 = mn % 9;
        float acc = 0.f;
        #pragma unroll
        for (int ha = 0; ha < 4; ha++)
            #pragma unroll
            for (int hb = 0; hb < 4; hb++) {
                int mm = 3 * ((ha >> 1) + (hb >> 1)) + ((ha & 1) + (hb & 1));
                if (mm != m9) continue;
                #pragma unroll
                for (int la = 0; la < 4; la++)
                    #pragma unroll
                    for (int lb = 0; lb < 4; lb++) {
                        int nn = 3 * ((la >> 1) + (lb >> 1)) + ((la & 1) + (lb & 1));
                        if (nn != n9) continue;
                        acc += sG[w][(4 * ha + la) * 16 + (4 * hb + lb)];
                    }
            }
        sD[tid] = acc;
    }
    __syncthreads();

    // ---- Phase C: D~ = K^T D' K, K = M (x) M, u_mon = M (1,C,S)^T ----
    if (tid < 243) {
        const float Mv[3][3] = {{0.5f, 0.5f, 0.f},
                                {0.f,  0.f,  0.5f},
                                {0.5f, -0.5f, 0.f}};
        int w = tid / 81;
        int pq = tid % 81;
        int p = pq / 9, q = pq % 9;
        int al = p / 3, gaq = p % 3;
        int al2 = q / 3, ga2 = q % 3;
        float Kp[9], Kq[9];
        #pragma unroll
        for (int m = 0; m < 9; m++) {
            Kp[m] = Mv[m / 3][al] * Mv[m % 3][gaq];
            Kq[m] = Mv[m / 3][al2] * Mv[m % 3][ga2];
        }
        float acc = 0.f;
        #pragma unroll
        for (int m = 0; m < 9; m++) {
            float r = 0.f;
            #pragma unroll
            for (int n = 0; n < 9; n++) r = fmaf(sD[w * 81 + m * 9 + n], Kq[n], r);
            acc = fmaf(Kp[m], r, acc);
        }
        g_CONST[tid] = acc;
    }
}

__global__ __launch_bounds__(128, 8) void qmain(const float4* __restrict__ x4,
                                                ulonglong2* __restrict__ out2)
{
    __shared__ float4 sQ[128];   // per element: {qi0, qi1, qi2, qi3}

    int tid = threadIdx.x;
    int lane = tid & 31, w = tid >> 5;
    int dq = lane & 15, half = lane >> 4;

    int gid = blockIdx.x * 128 + tid;
    float4 xv = x4[gid];

    // per-qubit full-angle C = cos(pi*tanh(x)), S = sin(pi*tanh(x))
    float C[4], S[4];
    {
        float xs[4] = {xv.x, xv.y, xv.z, xv.w};
        #pragma unroll
        for (int q = 0; q < 4; q++) {
            float e = __expf(2.f * xs[q]);
            float t = __fdividef(e - 1.f, e + 1.f);
            __sincosf(t * 3.14159265358979323846f, &S[q], &C[q]);
        }
    }

    // (1,C,S) Kronecker pairs, leading 1 implicit
    float v[8] = {C[1], S[1], C[0], C[0]*C[1], C[0]*S[1], S[0], S[0]*C[1], S[0]*S[1]};
    float u[8] = {C[3], S[3], C[2], C[2]*C[3], C[2]*S[3], S[2], S[2]*C[3], S[2]*S[3]};

    // z_w = v~^T D~_w u~ via constant bank (uniform datapath)
    float z1, z2, z3;
    #pragma unroll
    for (int m = 0; m < 9; m++) {
        float T1 = cCONST[      m * 9];
        float T2 = cCONST[ 81 + m * 9];
        float T3 = cCONST[162 + m * 9];
        #pragma unroll
        for (int n = 1; n < 9; n++) {
            T1 = fmaf(cCONST[      m * 9 + n], u[n - 1], T1);
            T2 = fmaf(cCONST[ 81 + m * 9 + n], u[n - 1], T2);
            T3 = fmaf(cCONST[162 + m * 9 + n], u[n - 1], T3);
        }
        if (m == 0) { z1 = T1; z2 = T2; z3 = T3; }
        else {
            z1 = fmaf(v[m - 1], T1, z1);
            z2 = fmaf(v[m - 1], T2, z2);
            z3 = fmaf(v[m - 1], T3, z3);
        }
    }

    // softmax numerators with e0 = 1; qi = e * rsqrt(e^T M''' e)
    float e1 = __expf(z1), e2 = __expf(z2), e3 = __expf(z3);
    float t0 = fmaf(cCONST[244], e1, cCONST[243]);
    t0 = fmaf(cCONST[245], e2, t0); t0 = fmaf(cCONST[246], e3, t0);
    float t1 = fmaf(cCONST[248], e1, cCONST[247]);
    t1 = fmaf(cCONST[249], e2, t1); t1 = fmaf(cCONST[250], e3, t1);
    float t2 = fmaf(cCONST[252], e1, cCONST[251]);
    t2 = fmaf(cCONST[253], e2, t2); t2 = fmaf(cCONST[254], e3, t2);
    float t3 = fmaf(cCONST[256], e1, cCONST[255]);
    t3 = fmaf(cCONST[257], e2, t3); t3 = fmaf(cCONST[258], e3, t3);
    float uu = fmaf(e1, t1, t0);
    uu = fmaf(e2, t2, uu);
    uu = fmaf(e3, t3, uu);
    float rr = rsqrtf(uu);

    sQ[tid] = make_float4(rr, e1 * rr, e2 * rr, e3 * rr);
    __syncwarp();

    // epilogue constants for this lane's dim quad (late load, short live range)
    const ulonglong2* ec2 = (const ulonglong2*)&g_epi4[dq][0];
    ulonglong2 EA = ec2[0], EB = ec2[1], EC = ec2[2], ED = ec2[3], EE = ec2[4];
    u64 WA0 = EA.x, WA1 = EA.y, WA2 = EB.x, WA3 = EB.y;
    u64 WB0 = EC.x, WB1 = EC.y, WB2 = ED.x, WB3 = ED.y;
    u64 B01 = EE.x, B23 = EE.y;

    // epilogue: lane owns dims [4dq, 4dq+4); half-warps serve elements 2it / 2it+1
    size_t ebase = (size_t)blockIdx.x * 128 + (size_t)w * 32 + half;
    #pragma unroll
    for (int it = 0; it < 16; it++) {
        int el = w * 32 + 2 * it + half;
        float4 q = sQ[el];
        u64 q0 = pk2(q.x, q.x), q1 = pk2(q.y, q.y);
        u64 q2 = pk2(q.z, q.z), q3 = pk2(q.w, q.w);
        u64 o01 = f2fma(WA0, q0, B01);
        o01 = f2fma(WA1, q1, o01);
        o01 = f2fma(WA2, q2, o01);
        o01 = f2fma(WA3, q3, o01);
        u64 o23 = f2fma(WB0, q0, B23);
        o23 = f2fma(WB1, q1, o23);
        o23 = f2fma(WB2, q2, o23);
        o23 = f2fma(WB3, q3, o23);
        out2[(ebase + 2 * it) * 16 + dq] = make_ulonglong2(o01, o23);
    }
}

extern "C" void kernel_launch(void* const* d_in, const int* in_sizes, int n_in,
                              void* d_out, int out_size)
{
    const float* x   = (const float*)d_in[0];
    const float* wts = (const float*)d_in[1];
    const float* W   = (const float*)d_in[2];
    const float* b   = (const float*)d_in[3];
    const float* gm  = (const float*)d_in[4];
    const float* bt  = (const float*)d_in[5];
    int B = in_sizes[0] / 4;

    setup_kernel<<<1, 256>>>(wts, W, b, gm, bt);

    void* src = nullptr;
    cudaGetSymbolAddress(&src, g_CONST);
    cudaMemcpyToSymbolAsync(cCONST, src, 260 * sizeof(float), 0,
                            cudaMemcpyDeviceToDevice);

    qmain<<<B / 128, 128>>>((const float4*)x, (ulonglong2*)d_out);
}

// round 12
// speedup vs baseline: 1.0701x; 1.0701x over previous
#include <cuda_runtime.h>

// ---------------------------------------------------------------------------
// QuantumBranch R11: cross-element f32x2 quadform. Each thread processes 2
// elements; every quadform FMA is fma.rn.f32x2 over {elemA, elemB} with
// constants pre-DUPLICATED {c,c} in __constant__ (LDCU.64, uniform path).
//   z_w - z_0 = v~^T D~_w u~ in the (1,C,S) Kronecker basis (leading 1
//   implicit). qi = e * rsqrt(e^T M''' e) scalar per element (M''' LDCU
//   shared). Epilogue: R8's warp-local transpose, 32 iters.
// Setup: R8's serial V-build (fastest measured) + Phase A/B + Phase C
// (basis change), writing duplicated constant pairs.
// ---------------------------------------------------------------------------

typedef unsigned long long u64;

// [0..486): dup pairs {c,c} of D~1,D~2,D~3 (81 u64 each); [486..502): M''' scalars
__device__ __align__(8)   float g_CONST[504];
__constant__ __align__(8) float cCONST[504];
__device__    float4 g_epi4[16][6];     // per dim-quad: 8 WA, 8 WB, 4 beta, pad

__device__ __forceinline__ u64 pk2(float a, float b) {
    u64 r; asm("mov.b64 %0,{%1,%2};" : "=l"(r) : "f"(a), "f"(b)); return r;
}
__device__ __forceinline__ void upk2(u64 v, float& a, float& b) {
    asm("mov.b64 {%0,%1},%2;" : "=f"(a), "=f"(b) : "l"(v));
}
__device__ __forceinline__ u64 f2fma(u64 a, u64 b, u64 c) {
    u64 d; asm("fma.rn.f32x2 %0,%1,%2,%3;" : "=l"(d) : "l"(a), "l"(b), "l"(c)); return d;
}

__device__ __forceinline__ float wsum(float v) {
    #pragma unroll
    for (int o = 16; o; o >>= 1) v += __shfl_xor_sync(0xffffffffu, v, o);
    return v;
}

__global__ void setup_kernel(const float* __restrict__ wts,
                             const float* __restrict__ W,
                             const float* __restrict__ b,
                             const float* __restrict__ gm,
                             const float* __restrict__ bt)
{
    __shared__ float2 sv[16][16];    // [col j][row k] = V[k][j]
    __shared__ float  sG[3][256];    // per (i,j) pair: G_w[i][j]
    __shared__ float  sD[243];       // D'_w in monomial basis
    int tid = threadIdx.x;

    // ---- warp0 lanes 0..15: serial register-resident V build (fastest) ----
    if (tid < 16) {
        int j = tid;
        float2 st[16];
        #pragma unroll
        for (int k = 0; k < 16; k++) st[k] = make_float2(k == j ? 1.f : 0.f, 0.f);

        #pragma unroll
        for (int l = 0; l < 2; l++) {
            #pragma unroll
            for (int w = 0; w < 4; w++) {
                const float* g = wts + (l * 4 + w) * 3;
                float phi = g[0], th = g[1], om = g[2];
                float a = 0.5f * (phi + om), bb = 0.5f * (phi - om), hh = 0.5f * th;
                float sa, ca, sb, cb, stt, ct;
                __sincosf(a, &sa, &ca);
                __sincosf(bb, &sb, &cb);
                __sincosf(hh, &stt, &ct);
                float2 g00 = make_float2( ca * ct, -sa * ct);
                float2 g01 = make_float2(-cb * stt, -sb * stt);
                float2 g10 = make_float2( cb * stt, -sb * stt);
                float2 g11 = make_float2( ca * ct,  sa * ct);
                int mask = 8 >> w;
                #pragma unroll
                for (int k = 0; k < 16; k++) {
                    if (!(k & mask)) {
                        int k1 = k | mask;
                        float2 A = st[k], Bv = st[k1];
                        float2 t0, t1;
                        t0.x = g00.x * A.x - g00.y * A.y + g01.x * Bv.x - g01.y * Bv.y;
                        t0.y = g00.x * A.y + g00.y * A.x + g01.x * Bv.y + g01.y * Bv.x;
                        t1.x = g10.x * A.x - g10.y * A.y + g11.x * Bv.x - g11.y * Bv.y;
                        t1.y = g10.x * A.y + g10.y * A.x + g11.x * Bv.y + g11.y * Bv.x;
                        st[k] = t0; st[k1] = t1;
                    }
                }
            }
            int r = (l == 0) ? 1 : 2;
            #pragma unroll
            for (int w = 0; w < 4; w++) {
                int mc = 8 >> w, mt = 8 >> ((w + r) & 3);
                #pragma unroll
                for (int k = 0; k < 16; k++) {
                    if ((k & mc) && !(k & mt)) {
                        float2 tmp = st[k]; st[k] = st[k | mt]; st[k | mt] = tmp;
                    }
                }
            }
        }
        int pop = __popc(j) & 3;
        #pragma unroll
        for (int k = 0; k < 16; k++) {
            float2 v = st[k], o;
            if      (pop == 0) o = v;
            else if (pop == 1) o = make_float2( v.y, -v.x);
            else if (pop == 2) o = make_float2(-v.x, -v.y);
            else               o = make_float2(-v.y,  v.x);
            sv[j][k] = o;
        }
    }

    // ---- warp1 (tid 32..63): LayerNorm folds -> M''' + epilogue consts ----
    if (tid >= 32 && tid < 64) {
        int lane = tid - 32;
        const float inv64 = 1.f / 64.f;
        float wa[4], wb[4];
        #pragma unroll
        for (int i = 0; i < 4; i++) { wa[i] = W[lane * 4 + i]; wb[i] = W[(lane + 32) * 4 + i]; }
        float ba = b[lane], bbv = b[lane + 32];

        float cm[4];
        #pragma unroll
        for (int i = 0; i < 4; i++) cm[i] = wsum(wa[i] + wb[i]) * inv64;
        float bm = wsum(ba + bbv) * inv64;
        #pragma unroll
        for (int i = 0; i < 4; i++) { wa[i] -= cm[i]; wb[i] -= cm[i]; }
        ba -= bm; bbv -= bm;

        float M[4][4];
        #pragma unroll
        for (int i = 0; i < 4; i++) {
            #pragma unroll
            for (int k = 0; k < 4; k++) {
                if (k >= i) {
                    float v = wsum(wa[i] * wa[k] + wb[i] * wb[k]) * inv64;
                    M[i][k] = v; M[k][i] = v;
                }
            }
        }
        float vv[4];
        #pragma unroll
        for (int i = 0; i < 4; i++) vv[i] = wsum(wa[i] * ba + wb[i] * bbv) * (2.f * inv64);
        float vc = wsum(ba * ba + bbv * bbv) * inv64;

        if (lane == 0) {
            #pragma unroll
            for (int i = 0; i < 4; i++)
                #pragma unroll
                for (int k = 0; k < 4; k++)
                    g_CONST[486 + i * 4 + k] =
                        M[i][k] + 0.5f * (vv[i] + vv[k]) + vc + 1e-5f;
        }

        float ga = gm[lane], gb = gm[lane + 32];
        float bea = bt[lane], beb = bt[lane + 32];
        {
            int d = lane, dqi = d >> 2, r = d & 3;
            float* ep = (float*)&g_epi4[dqi][0];
            int base = (r < 2) ? r : (8 + (r - 2));
            ep[base + 0] = (wa[0] + ba) * ga;
            ep[base + 2] = (wa[1] + ba) * ga;
            ep[base + 4] = (wa[2] + ba) * ga;
            ep[base + 6] = (wa[3] + ba) * ga;
            ep[16 + r]   = bea;
        }
        {
            int d = lane + 32, dqi = d >> 2, r = d & 3;
            float* ep = (float*)&g_epi4[dqi][0];
            int base = (r < 2) ? r : (8 + (r - 2));
            ep[base + 0] = (wb[0] + bbv) * gb;
            ep[base + 2] = (wb[1] + bbv) * gb;
            ep[base + 4] = (wb[2] + bbv) * gb;
            ep[base + 6] = (wb[3] + bbv) * gb;
            ep[16 + r]   = beb;
        }
    }

    __syncthreads();

    // ---- Phase A: per (i,j) pair, G_w[i][j] = sum_k (sigma_w - sigma_0) Re(V*_i V_j)
    {
        int i = tid >> 4, j = tid & 15;
        float g1 = 0.f, g2 = 0.f, g3 = 0.f;
        #pragma unroll
        for (int k = 0; k < 16; k++) {
            float rr = sv[i][k].x * sv[j][k].x + sv[i][k].y * sv[j][k].y;
            float s0 = (k & 8) ? -1.f : 1.f;
            g1 += (((k & 4) ? -1.f : 1.f) - s0) * rr;
            g2 += (((k & 2) ? -1.f : 1.f) - s0) * rr;
            g3 += (((k & 1) ? -1.f : 1.f) - s0) * rr;
        }
        sG[0][tid] = g1; sG[1][tid] = g2; sG[2][tid] = g3;
    }
    __syncthreads();

    // ---- Phase B: D'_w[m9][n9] (monomial basis) ----
    if (tid < 243) {
        int w = tid / 81;
        int mn = tid % 81;
        int m9 = mn / 9, n9 = mn % 9;
        float acc = 0.f;
        #pragma unroll
        for (int ha = 0; ha < 4; ha++)
            #pragma unroll
            for (int hb = 0; hb < 4; hb++) {
                int mm = 3 * ((ha >> 1) + (hb >> 1)) + ((ha & 1) + (hb & 1));
                if (mm != m9) continue;
                #pragma unroll
                for (int la = 0; la < 4; la++)
                    #pragma unroll
                    for (int lb = 0; lb < 4; lb++) {
                        int nn = 3 * ((la >> 1) + (lb >> 1)) + ((la & 1) + (lb & 1));
                        if (nn != n9) continue;
                        acc += sG[w][(4 * ha + la) * 16 + (4 * hb + lb)];
                    }
            }
        sD[tid] = acc;
    }
    __syncthreads();

    // ---- Phase C: D~ = K^T D' K (basis (1,C,S)); write DUPLICATED pairs ----
    if (tid < 243) {
        const float Mv[3][3] = {{0.5f, 0.5f, 0.f},
                                {0.f,  0.f,  0.5f},
                                {0.5f, -0.5f, 0.f}};
        int w = tid / 81;
        int pq = tid % 81;
        int p = pq / 9, q = pq % 9;
        int al = p / 3, gaq = p % 3;
        int al2 = q / 3, ga2 = q % 3;
        float Kp[9], Kq[9];
        #pragma unroll
        for (int m = 0; m < 9; m++) {
            Kp[m] = Mv[m / 3][al] * Mv[m % 3][gaq];
            Kq[m] = Mv[m / 3][al2] * Mv[m % 3][ga2];
        }
        float acc = 0.f;
        #pragma unroll
        for (int m = 0; m < 9; m++) {
            float r = 0.f;
            #pragma unroll
            for (int n = 0; n < 9; n++) r = fmaf(sD[w * 81 + m * 9 + n], Kq[n], r);
            acc = fmaf(Kp[m], r, acc);
        }
        g_CONST[2 * tid]     = acc;   // duplicated pair for f32x2
        g_CONST[2 * tid + 1] = acc;
    }
}

__global__ __launch_bounds__(128, 8) void qmain(const float4* __restrict__ x4,
                                                ulonglong2* __restrict__ out2)
{
    __shared__ float4 sQ[256];   // per element: {qi0, qi1, qi2, qi3}

    int tid = threadIdx.x;
    int lane = tid & 31, w = tid >> 5;
    int dq = lane & 15, half = lane >> 4;

    int gbase = blockIdx.x * 256;
    int eA = w * 64 + lane;           // block-relative; eB = eA + 32
    float4 xA = x4[gbase + eA];
    float4 xB = x4[gbase + eA + 32];

    // per-qubit full-angle C = cos(pi*tanh(x)), S = sin(pi*tanh(x))
    float CA[4], SA[4], CB[4], SB[4];
    {
        float xsA[4] = {xA.x, xA.y, xA.z, xA.w};
        float xsB[4] = {xB.x, xB.y, xB.z, xB.w};
        #pragma unroll
        for (int q = 0; q < 4; q++) {
            float ea = __expf(2.f * xsA[q]);
            float ta = __fdividef(ea - 1.f, ea + 1.f);
            __sincosf(ta * 3.14159265358979323846f, &SA[q], &CA[q]);
            float eb = __expf(2.f * xsB[q]);
            float tb = __fdividef(eb - 1.f, eb + 1.f);
            __sincosf(tb * 3.14159265358979323846f, &SB[q], &CB[q]);
        }
    }

    // (1,C,S) Kronecker pairs (leading 1 implicit):
    //   v scalars per element (qubits 0,1); u cross-element packed {A,B} (qubits 2,3)
    float vA[8] = {CA[1], SA[1], CA[0], CA[0]*CA[1], CA[0]*SA[1],
                   SA[0], SA[0]*CA[1], SA[0]*SA[1]};
    float vB[8] = {CB[1], SB[1], CB[0], CB[0]*CB[1], CB[0]*SB[1],
                   SB[0], SB[0]*CB[1], SB[0]*SB[1]};
    u64 uab[8];
    uab[0] = pk2(CA[3], CB[3]);
    uab[1] = pk2(SA[3], SB[3]);
    uab[2] = pk2(CA[2], CB[2]);
    uab[3] = pk2(CA[2]*CA[3], CB[2]*CB[3]);
    uab[4] = pk2(CA[2]*SA[3], CB[2]*SB[3]);
    uab[5] = pk2(SA[2], SB[2]);
    uab[6] = pk2(SA[2]*CA[3], SB[2]*CB[3]);
    uab[7] = pk2(SA[2]*SA[3], SB[2]*SB[3]);

    // quadform: z_w packed {z_wA, z_wB}; constants are dup pairs via LDCU.64
    const u64* CD = (const u64*)cCONST;
    u64 z1, z2, z3;
    #pragma unroll
    for (int m = 0; m < 9; m++) {
        // T_w = c[m][0] + sum_n c[m][n] * u[n]   (8 f2fma, addend = leading const)
        u64 T1 = f2fma(CD[      m * 9 + 1], uab[0], CD[      m * 9]);
        u64 T2 = f2fma(CD[ 81 + m * 9 + 1], uab[0], CD[ 81 + m * 9]);
        u64 T3 = f2fma(CD[162 + m * 9 + 1], uab[0], CD[162 + m * 9]);
        #pragma unroll
        for (int n = 2; n < 9; n++) {
            T1 = f2fma(CD[      m * 9 + n], uab[n - 1], T1);
            T2 = f2fma(CD[ 81 + m * 9 + n], uab[n - 1], T2);
            T3 = f2fma(CD[162 + m * 9 + n], uab[n - 1], T3);
        }
        if (m == 0) { z1 = T1; z2 = T2; z3 = T3; }
        else {
            u64 vab = pk2(vA[m - 1], vB[m - 1]);
            z1 = f2fma(vab, T1, z1);
            z2 = f2fma(vab, T2, z2);
            z3 = f2fma(vab, T3, z3);
        }
    }
    float z1A, z1B, z2A, z2B, z3A, z3B;
    upk2(z1, z1A, z1B); upk2(z2, z2A, z2B); upk2(z3, z3A, z3B);

    // softmax numerators (e0=1); qi = e * rsqrt(e^T M''' e) -- scalar, M''' shared
    {
        float e1 = __expf(z1A), e2 = __expf(z2A), e3 = __expf(z3A);
        float t0 = fmaf(cCONST[487], e1, cCONST[486]);
        t0 = fmaf(cCONST[488], e2, t0); t0 = fmaf(cCONST[489], e3, t0);
        float t1 = fmaf(cCONST[491], e1, cCONST[490]);
        t1 = fmaf(cCONST[492], e2, t1); t1 = fmaf(cCONST[493], e3, t1);
        float t2 = fmaf(cCONST[495], e1, cCONST[494]);
        t2 = fmaf(cCONST[496], e2, t2); t2 = fmaf(cCONST[497], e3, t2);
        float t3 = fmaf(cCONST[499], e1, cCONST[498]);
        t3 = fmaf(cCONST[500], e2, t3); t3 = fmaf(cCONST[501], e3, t3);
        float uu = fmaf(e1, t1, t0);
        uu = fmaf(e2, t2, uu);
        uu = fmaf(e3, t3, uu);
        float rr = rsqrtf(uu);
        sQ[eA] = make_float4(rr, e1 * rr, e2 * rr, e3 * rr);
    }
    {
        float e1 = __expf(z1B), e2 = __expf(z2B), e3 = __expf(z3B);
        float t0 = fmaf(cCONST[487], e1, cCONST[486]);
        t0 = fmaf(cCONST[488], e2, t0); t0 = fmaf(cCONST[489], e3, t0);
        float t1 = fmaf(cCONST[491], e1, cCONST[490]);
        t1 = fmaf(cCONST[492], e2, t1); t1 = fmaf(cCONST[493], e3, t1);
        float t2 = fmaf(cCONST[495], e1, cCONST[494]);
        t2 = fmaf(cCONST[496], e2, t2); t2 = fmaf(cCONST[497], e3, t2);
        float t3 = fmaf(cCONST[499], e1, cCONST[498]);
        t3 = fmaf(cCONST[500], e2, t3); t3 = fmaf(cCONST[501], e3, t3);
        float uu = fmaf(e1, t1, t0);
        uu = fmaf(e2, t2, uu);
        uu = fmaf(e3, t3, uu);
        float rr = rsqrtf(uu);
        sQ[eA + 32] = make_float4(rr, e1 * rr, e2 * rr, e3 * rr);
    }
    __syncwarp();

    // epilogue constants for this lane's dim quad (late load, short live range)
    const ulonglong2* ec2 = (const ulonglong2*)&g_epi4[dq][0];
    ulonglong2 EA = ec2[0], EB = ec2[1], EC = ec2[2], ED = ec2[3], EE = ec2[4];
    u64 WA0 = EA.x, WA1 = EA.y, WA2 = EB.x, WA3 = EB.y;
    u64 WB0 = EC.x, WB1 = EC.y, WB2 = ED.x, WB3 = ED.y;
    u64 B01 = EE.x, B23 = EE.y;

    // epilogue: lane owns dims [4dq, 4dq+4); half-warps serve elements 2it / 2it+1
    #pragma unroll
    for (int it = 0; it < 32; it++) {
        int el = w * 64 + 2 * it + half;
        float4 q = sQ[el];
        u64 q0 = pk2(q.x, q.x), q1 = pk2(q.y, q.y);
        u64 q2 = pk2(q.z, q.z), q3 = pk2(q.w, q.w);
        u64 o01 = f2fma(WA0, q0, B01);
        o01 = f2fma(WA1, q1, o01);
        o01 = f2fma(WA2, q2, o01);
        o01 = f2fma(WA3, q3, o01);
        u64 o23 = f2fma(WB0, q0, B23);
        o23 = f2fma(WB1, q1, o23);
        o23 = f2fma(WB2, q2, o23);
        o23 = f2fma(WB3, q3, o23);
        out2[((size_t)gbase + el) * 16 + dq] = make_ulonglong2(o01, o23);
    }
}

extern "C" void kernel_launch(void* const* d_in, const int* in_sizes, int n_in,
                              void* d_out, int out_size)
{
    const float* x   = (const float*)d_in[0];
    const float* wts = (const float*)d_in[1];
    const float* W   = (const float*)d_in[2];
    const float* b   = (const float*)d_in[3];
    const float* gm  = (const float*)d_in[4];
    const float* bt  = (const float*)d_in[5];
    int B = in_sizes[0] / 4;

    setup_kernel<<<1, 256>>>(wts, W, b, gm, bt);

    void* src = nullptr;
    cudaGetSymbolAddress(&src, g_CONST);
    cudaMemcpyToSymbolAsync(cCONST, src, 504 * sizeof(float), 0,
                            cudaMemcpyDeviceToDevice);

    qmain<<<B / 256, 128>>>((const float4*)x, (ulonglong2*)d_out);
}

// round 13
// speedup vs baseline: 1.0911x; 1.0196x over previous
#include <cuda_runtime.h>

// ---------------------------------------------------------------------------
// QuantumBranch R12: R8's proven kernel with occupancy raised from 8 to 10
// blocks/SM (__launch_bounds__(128,10) -> <=48 regs). qmain was shown to be
// latency-bound (no pipe saturated, occ RF-capped at 64 regs x 32 warps);
// +25% resident warps is the only lever that moves a latency-bound kernel.
//   z_w - z_0 = PP9^T D'_w QQ9 (9-monomial quadform, __constant__/uniform
//   datapath). qi = e * rsqrt(e^T M''' e). Warp-local transpose epilogue.
// ---------------------------------------------------------------------------

typedef unsigned long long u64;

__device__    float g_CONST[260];       // [0..243): D'1,D'2,D'3 (81 each); [243..259): M'''
__constant__  float cCONST[260];
__device__    float4 g_epi4[16][6];     // per dim-quad: 8 WA, 8 WB, 4 beta, pad

__device__ __forceinline__ u64 pk2(float a, float b) {
    u64 r; asm("mov.b64 %0,{%1,%2};" : "=l"(r) : "f"(a), "f"(b)); return r;
}
__device__ __forceinline__ u64 f2fma(u64 a, u64 b, u64 c) {
    u64 d; asm("fma.rn.f32x2 %0,%1,%2,%3;" : "=l"(d) : "l"(a), "l"(b), "l"(c)); return d;
}

__device__ __forceinline__ float wsum(float v) {
    #pragma unroll
    for (int o = 16; o; o >>= 1) v += __shfl_xor_sync(0xffffffffu, v, o);
    return v;
}

__global__ void setup_kernel(const float* __restrict__ wts,
                             const float* __restrict__ W,
                             const float* __restrict__ b,
                             const float* __restrict__ gm,
                             const float* __restrict__ bt)
{
    __shared__ float2 sv[16][16];    // [col j][row k] = V[k][j]
    __shared__ float  sG[3][256];    // per (i,j) pair: G_w[i][j]
    int tid = threadIdx.x;

    // ---- warp0 lanes 0..15: serial register-resident V build ----
    if (tid < 16) {
        int j = tid;
        float2 st[16];
        #pragma unroll
        for (int k = 0; k < 16; k++) st[k] = make_float2(k == j ? 1.f : 0.f, 0.f);

        #pragma unroll
        for (int l = 0; l < 2; l++) {
            #pragma unroll
            for (int w = 0; w < 4; w++) {
                const float* g = wts + (l * 4 + w) * 3;
                float phi = g[0], th = g[1], om = g[2];
                float a = 0.5f * (phi + om), bb = 0.5f * (phi - om), hh = 0.5f * th;
                float sa, ca, sb, cb, stt, ct;
                __sincosf(a, &sa, &ca);
                __sincosf(bb, &sb, &cb);
                __sincosf(hh, &stt, &ct);
                float2 g00 = make_float2( ca * ct, -sa * ct);
                float2 g01 = make_float2(-cb * stt, -sb * stt);
                float2 g10 = make_float2( cb * stt, -sb * stt);
                float2 g11 = make_float2( ca * ct,  sa * ct);
                int mask = 8 >> w;
                #pragma unroll
                for (int k = 0; k < 16; k++) {
                    if (!(k & mask)) {
                        int k1 = k | mask;
                        float2 A = st[k], Bv = st[k1];
                        float2 t0, t1;
                        t0.x = g00.x * A.x - g00.y * A.y + g01.x * Bv.x - g01.y * Bv.y;
                        t0.y = g00.x * A.y + g00.y * A.x + g01.x * Bv.y + g01.y * Bv.x;
                        t1.x = g10.x * A.x - g10.y * A.y + g11.x * Bv.x - g11.y * Bv.y;
                        t1.y = g10.x * A.y + g10.y * A.x + g11.x * Bv.y + g11.y * Bv.x;
                        st[k] = t0; st[k1] = t1;
                    }
                }
            }
            int r = (l == 0) ? 1 : 2;
            #pragma unroll
            for (int w = 0; w < 4; w++) {
                int mc = 8 >> w, mt = 8 >> ((w + r) & 3);
                #pragma unroll
                for (int k = 0; k < 16; k++) {
                    if ((k & mc) && !(k & mt)) {
                        float2 tmp = st[k]; st[k] = st[k | mt]; st[k | mt] = tmp;
                    }
                }
            }
        }
        int pop = __popc(j) & 3;
        #pragma unroll
        for (int k = 0; k < 16; k++) {
            float2 v = st[k], o;
            if      (pop == 0) o = v;
            else if (pop == 1) o = make_float2( v.y, -v.x);
            else if (pop == 2) o = make_float2(-v.x, -v.y);
            else               o = make_float2(-v.y,  v.x);
            sv[j][k] = o;
        }
    }

    // ---- warp1 (tid 32..63): LayerNorm folds -> M''' + epilogue consts ----
    if (tid >= 32 && tid < 64) {
        int lane = tid - 32;
        const float inv64 = 1.f / 64.f;
        float wa[4], wb[4];
        #pragma unroll
        for (int i = 0; i < 4; i++) { wa[i] = W[lane * 4 + i]; wb[i] = W[(lane + 32) * 4 + i]; }
        float ba = b[lane], bbv = b[lane + 32];

        float cm[4];
        #pragma unroll
        for (int i = 0; i < 4; i++) cm[i] = wsum(wa[i] + wb[i]) * inv64;
        float bm = wsum(ba + bbv) * inv64;
        #pragma unroll
        for (int i = 0; i < 4; i++) { wa[i] -= cm[i]; wb[i] -= cm[i]; }
        ba -= bm; bbv -= bm;

        float M[4][4];
        #pragma unroll
        for (int i = 0; i < 4; i++) {
            #pragma unroll
            for (int k = 0; k < 4; k++) {
                if (k >= i) {
                    float v = wsum(wa[i] * wa[k] + wb[i] * wb[k]) * inv64;
                    M[i][k] = v; M[k][i] = v;
                }
            }
        }
        float vv[4];
        #pragma unroll
        for (int i = 0; i < 4; i++) vv[i] = wsum(wa[i] * ba + wb[i] * bbv) * (2.f * inv64);
        float vc = wsum(ba * ba + bbv * bbv) * inv64;

        if (lane == 0) {
            #pragma unroll
            for (int i = 0; i < 4; i++)
                #pragma unroll
                for (int k = 0; k < 4; k++)
                    g_CONST[243 + i * 4 + k] =
                        M[i][k] + 0.5f * (vv[i] + vv[k]) + vc + 1e-5f;
        }

        float ga = gm[lane], gb = gm[lane + 32];
        float bea = bt[lane], beb = bt[lane + 32];
        {
            int d = lane, dqi = d >> 2, r = d & 3;
            float* ep = (float*)&g_epi4[dqi][0];
            int base = (r < 2) ? r : (8 + (r - 2));
            ep[base + 0] = (wa[0] + ba) * ga;
            ep[base + 2] = (wa[1] + ba) * ga;
            ep[base + 4] = (wa[2] + ba) * ga;
            ep[base + 6] = (wa[3] + ba) * ga;
            ep[16 + r]   = bea;
        }
        {
            int d = lane + 32, dqi = d >> 2, r = d & 3;
            float* ep = (float*)&g_epi4[dqi][0];
            int base = (r < 2) ? r : (8 + (r - 2));
            ep[base + 0] = (wb[0] + bbv) * gb;
            ep[base + 2] = (wb[1] + bbv) * gb;
            ep[base + 4] = (wb[2] + bbv) * gb;
            ep[base + 6] = (wb[3] + bbv) * gb;
            ep[16 + r]   = beb;
        }
    }

    __syncthreads();

    // ---- Phase A: per (i,j) pair, G_w[i][j] = sum_k (sigma_w - sigma_0) Re(V*_i V_j)
    {
        int i = tid >> 4, j = tid & 15;
        float g1 = 0.f, g2 = 0.f, g3 = 0.f;
        #pragma unroll
        for (int k = 0; k < 16; k++) {
            float rr = sv[i][k].x * sv[j][k].x + sv[i][k].y * sv[j][k].y;
            float s0 = (k & 8) ? -1.f : 1.f;
            g1 += (((k & 4) ? -1.f : 1.f) - s0) * rr;
            g2 += (((k & 2) ? -1.f : 1.f) - s0) * rr;
            g3 += (((k & 1) ? -1.f : 1.f) - s0) * rr;
        }
        sG[0][tid] = g1; sG[1][tid] = g2; sG[2][tid] = g3;
    }
    __syncthreads();

    // ---- Phase B: D'_w[m9][n9] ----
    if (tid < 243) {
        int w = tid / 81;
        int mn = tid % 81;
        int m9 = mn / 9, n9 = mn % 9;
        float acc = 0.f;
        #pragma unroll
        for (int ha = 0; ha < 4; ha++)
            #pragma unroll
            for (int hb = 0; hb < 4; hb++) {
                int mm = 3 * ((ha >> 1) + (hb >> 1)) + ((ha & 1) + (hb & 1));
                if (mm != m9) continue;
                #pragma unroll
                for (int la = 0; la < 4; la++)
                    #pragma unroll
                    for (int lb = 0; lb < 4; lb++) {
                        int nn = 3 * ((la >> 1) + (lb >> 1)) + ((la & 1) + (lb & 1));
                        if (nn != n9) continue;
                        acc += sG[w][(4 * ha + la) * 16 + (4 * hb + lb)];
                    }
            }
        g_CONST[tid] = acc;
    }
}

__global__ __launch_bounds__(128, 10) void qmain(const float4* __restrict__ x4,
                                                 ulonglong2* __restrict__ out2)
{
    __shared__ float4 sQ[128];   // per element: {qi0, qi1, qi2, qi3}

    int tid = threadIdx.x;
    int lane = tid & 31, w = tid >> 5;
    int dq = lane & 15, half = lane >> 4;

    int gid = blockIdx.x * 128 + tid;
    float4 xv = x4[gid];

    // tanh via exp, half-angle sincos
    float cc[4], ss[4];
    {
        float xs[4] = {xv.x, xv.y, xv.z, xv.w};
        #pragma unroll
        for (int q = 0; q < 4; q++) {
            float e  = __expf(2.f * xs[q]);
            float th = __fdividef(e - 1.f, e + 1.f);
            __sincosf(th * 1.5707963267948966f, &ss[q], &cc[q]);
        }
    }

    // monomial 9-vectors: u = (c^2, c*s, s^2) per qubit; PP9 = u0 (x) u1, QQ9 = u2 (x) u3
    float U0[3] = {cc[0]*cc[0], cc[0]*ss[0], ss[0]*ss[0]};
    float U1[3] = {cc[1]*cc[1], cc[1]*ss[1], ss[1]*ss[1]};
    float U2[3] = {cc[2]*cc[2], cc[2]*ss[2], ss[2]*ss[2]};
    float U3[3] = {cc[3]*cc[3], cc[3]*ss[3], ss[3]*ss[3]};
    float PP[9], QQ[9];
    #pragma unroll
    for (int a = 0; a < 3; a++)
        #pragma unroll
        for (int c = 0; c < 3; c++) {
            PP[3*a + c] = U0[a] * U1[c];
            QQ[3*a + c] = U2[a] * U3[c];
        }

    // z-differences via constant-bank quadform (uniform datapath, no L1)
    float z1 = 0.f, z2 = 0.f, z3 = 0.f;
    #pragma unroll
    for (int m = 0; m < 9; m++) {
        float T1 = cCONST[      m * 9] * QQ[0];
        float T2 = cCONST[ 81 + m * 9] * QQ[0];
        float T3 = cCONST[162 + m * 9] * QQ[0];
        #pragma unroll
        for (int n = 1; n < 9; n++) {
            T1 = fmaf(cCONST[      m * 9 + n], QQ[n], T1);
            T2 = fmaf(cCONST[ 81 + m * 9 + n], QQ[n], T2);
            T3 = fmaf(cCONST[162 + m * 9 + n], QQ[n], T3);
        }
        z1 = fmaf(PP[m], T1, z1);
        z2 = fmaf(PP[m], T2, z2);
        z3 = fmaf(PP[m], T3, z3);
    }

    // softmax numerators with e0 = 1 (shift-invariant); qi = e * rsqrt(e^T M''' e)
    float e1 = __expf(z1), e2 = __expf(z2), e3 = __expf(z3);
    float t0 = fmaf(cCONST[244], e1, cCONST[243]);
    t0 = fmaf(cCONST[245], e2, t0); t0 = fmaf(cCONST[246], e3, t0);
    float t1 = fmaf(cCONST[248], e1, cCONST[247]);
    t1 = fmaf(cCONST[249], e2, t1); t1 = fmaf(cCONST[250], e3, t1);
    float t2 = fmaf(cCONST[252], e1, cCONST[251]);
    t2 = fmaf(cCONST[253], e2, t2); t2 = fmaf(cCONST[254], e3, t2);
    float t3 = fmaf(cCONST[256], e1, cCONST[255]);
    t3 = fmaf(cCONST[257], e2, t3); t3 = fmaf(cCONST[258], e3, t3);
    float uu = fmaf(e1, t1, t0);
    uu = fmaf(e2, t2, uu);
    uu = fmaf(e3, t3, uu);
    float rr = rsqrtf(uu);

    sQ[tid] = make_float4(rr, e1 * rr, e2 * rr, e3 * rr);
    __syncwarp();

    // epilogue constants for this lane's dim quad (late load, short live range)
    const ulonglong2* ec2 = (const ulonglong2*)&g_epi4[dq][0];
    ulonglong2 EA = ec2[0], EB = ec2[1], EC = ec2[2], ED = ec2[3], EE = ec2[4];
    u64 WA0 = EA.x, WA1 = EA.y, WA2 = EB.x, WA3 = EB.y;
    u64 WB0 = EC.x, WB1 = EC.y, WB2 = ED.x, WB3 = ED.y;
    u64 B01 = EE.x, B23 = EE.y;

    // epilogue: lane owns dims [4dq, 4dq+4); half-warps serve elements 2it / 2it+1
    size_t ebase = (size_t)blockIdx.x * 128 + (size_t)w * 32 + half;
    #pragma unroll
    for (int it = 0; it < 16; it++) {
        int el = w * 32 + 2 * it + half;
        float4 q = sQ[el];
        u64 q0 = pk2(q.x, q.x), q1 = pk2(q.y, q.y);
        u64 q2 = pk2(q.z, q.z), q3 = pk2(q.w, q.w);
        u64 o01 = f2fma(WA0, q0, B01);
        o01 = f2fma(WA1, q1, o01);
        o01 = f2fma(WA2, q2, o01);
        o01 = f2fma(WA3, q3, o01);
        u64 o23 = f2fma(WB0, q0, B23);
        o23 = f2fma(WB1, q1, o23);
        o23 = f2fma(WB2, q2, o23);
        o23 = f2fma(WB3, q3, o23);
        out2[(ebase + 2 * it) * 16 + dq] = make_ulonglong2(o01, o23);
    }
}

extern "C" void kernel_launch(void* const* d_in, const int* in_sizes, int n_in,
                              void* d_out, int out_size)
{
    const float* x   = (const float*)d_in[0];
    const float* wts = (const float*)d_in[1];
    const float* W   = (const float*)d_in[2];
    const float* b   = (const float*)d_in[3];
    const float* gm  = (const float*)d_in[4];
    const float* bt  = (const float*)d_in[5];
    int B = in_sizes[0] / 4;

    setup_kernel<<<1, 256>>>(wts, W, b, gm, bt);

    void* src = nullptr;
    cudaGetSymbolAddress(&src, g_CONST);
    cudaMemcpyToSymbolAsync(cCONST, src, 260 * sizeof(float), 0,
                            cudaMemcpyDeviceToDevice);

    qmain<<<B / 128, 128>>>((const float4*)x, (ulonglong2*)d_out);
}